// round 1
// baseline (speedup 1.0000x reference)
#include <cuda_runtime.h>
#include <math.h>

#define BB   2
#define TT   16
#define NN   2048
#define CI1  32
#define CHH  64
#define CO   64
#define KS   3
#define EE   32768
#define T1   14
#define T2   12
#define F1   (BB*T1*CHH)   /* 1792 floats per node for propagation */
#define F14  (F1/4)        /* 448 float4 */

// ---------------- scratch (device globals; no allocations allowed) ----------
__device__ float g_t1 [NN*BB*T1*CHH];   // tconv1 out, node-major (n,b,t,c)
__device__ float g_tx1[NN*BB*T1*CHH];   // Tx1
__device__ float g_tx2[NN*BB*T1*CHH];   // Tx2
__device__ float g_t2 [NN*BB*T1*CHH];   // cheb+relu out
__device__ float g_t3 [NN*BB*T2*CO];    // tconv2 out, node-major
__device__ float g_deg[NN];
__device__ float g_dis[NN];
__device__ int   g_rowcount[NN];
__device__ int   g_rowstart[NN+1];
__device__ int   g_cursor[NN];
__device__ int   g_ccol[EE];
__device__ float g_cnorm[EE];

// ---------------- graph preprocessing ---------------------------------------
__global__ void k_zero() {
    int i = blockIdx.x * blockDim.x + threadIdx.x;
    if (i < NN) { g_deg[i] = 0.f; g_rowcount[i] = 0; g_cursor[i] = 0; }
}

__global__ void k_deg(const int* __restrict__ ei, const float* __restrict__ ew) {
    int e = blockIdx.x * blockDim.x + threadIdx.x;
    if (e < EE) {
        int r = ei[e], c = ei[EE + e];
        float w = (r == c) ? 0.f : ew[e];
        atomicAdd(&g_deg[r], w);
        atomicAdd(&g_rowcount[r], 1);
    }
}

__global__ void k_dis() {
    int i = blockIdx.x * blockDim.x + threadIdx.x;
    if (i < NN) {
        float d = g_deg[i];
        g_dis[i] = (d > 0.f) ? rsqrtf(d) : 0.f;
    }
}

// single block, 1024 threads: Hillis-Steele inclusive scan over 2048 counts
__global__ void k_scan() {
    __shared__ int s[NN];
    int tid = threadIdx.x;
    s[tid]        = g_rowcount[tid];
    s[tid + 1024] = g_rowcount[tid + 1024];
    __syncthreads();
    for (int off = 1; off < NN; off <<= 1) {
        int i0 = tid, i1 = tid + 1024;
        int v0 = s[i0] + ((i0 >= off) ? s[i0 - off] : 0);
        int v1 = s[i1] + ((i1 >= off) ? s[i1 - off] : 0);
        __syncthreads();
        s[i0] = v0; s[i1] = v1;
        __syncthreads();
    }
    g_rowstart[tid + 1]    = s[tid];
    g_rowstart[tid + 1025] = s[tid + 1024];
    if (tid == 0) g_rowstart[0] = 0;
}

__global__ void k_scatter(const int* __restrict__ ei, const float* __restrict__ ew) {
    int e = blockIdx.x * blockDim.x + threadIdx.x;
    if (e < EE) {
        int r = ei[e], c = ei[EE + e];
        float w = (r == c) ? 0.f : ew[e];
        int pos = g_rowstart[r] + atomicAdd(&g_cursor[r], 1);
        g_ccol[pos]  = c;
        g_cnorm[pos] = -g_dis[r] * w * g_dis[c];
    }
}

// ---------------- gated temporal conv ---------------------------------------
// Thread layout: 512 threads = 8 (n,b) groups x 64 channels.
// x loads are warp-uniform (same (n,b) across a 64-thread group);
// weights in smem with lane-contiguous ch => conflict-free broadcast pattern.
template<int CI, int TIN>
__global__ void __launch_bounds__(512) k_tconv(
    const float* __restrict__ x, long sb, long st, long sn,
    const float* __restrict__ w1, const float* __restrict__ bb1,
    const float* __restrict__ w2, const float* __restrict__ bb2,
    const float* __restrict__ w3, const float* __restrict__ bb3,
    float* __restrict__ out)
{
    constexpr int TOUT = TIN - 2;
    extern __shared__ float sw[];  // [3][CI][3][64]
    for (int idx = threadIdx.x; idx < 3 * CI * 3 * 64; idx += 512) {
        int ch = idx & 63;
        int rest = idx >> 6;
        int k = rest % 3; rest /= 3;
        int ci = rest % CI;
        int j  = rest / CI;
        const float* wj = (j == 0) ? w1 : ((j == 1) ? w2 : w3);
        sw[idx] = wj[(ch * CI + ci) * KS + k];
    }
    __syncthreads();

    int ch = threadIdx.x & 63;
    int g  = threadIdx.x >> 6;
    int nb = blockIdx.x * 8 + g;
    int n  = nb >> 1, b = nb & 1;

    float acc[3][TOUT];
#pragma unroll
    for (int j = 0; j < 3; j++)
#pragma unroll
        for (int t = 0; t < TOUT; t++) acc[j][t] = 0.f;

    const float* xb = x + (long)b * sb + (long)n * sn;

    for (int ci = 0; ci < CI; ci++) {
        float w[3][3];
#pragma unroll
        for (int j = 0; j < 3; j++)
#pragma unroll
            for (int k = 0; k < 3; k++)
                w[j][k] = sw[((j * CI + ci) * 3 + k) * 64 + ch];
#pragma unroll
        for (int ti = 0; ti < TIN; ti++) {
            float xv = __ldg(xb + (long)ti * st + ci);
#pragma unroll
            for (int k = 0; k < 3; k++) {
                int to = ti - k;
                if (to >= 0 && to < TOUT) {
                    acc[0][to] += xv * w[0][k];
                    acc[1][to] += xv * w[1][k];
                    acc[2][to] += xv * w[2][k];
                }
            }
        }
    }

    float bv1 = __ldg(bb1 + ch), bv2 = __ldg(bb2 + ch), bv3 = __ldg(bb3 + ch);
    float* ob = out + ((long)nb * TOUT) * 64 + ch;
#pragma unroll
    for (int t = 0; t < TOUT; t++) {
        float a1 = acc[0][t] + bv1;
        float a2 = acc[1][t] + bv2;
        float a3 = acc[2][t] + bv3;
        float sg = 1.f / (1.f + expf(-a2));
        float v  = a1 + sg + a3;
        ob[t * 64] = (v > 0.f) ? v : 0.f;
    }
}

// ---------------- ChebConv propagation (CSR gather) --------------------------
// one block per node, 448 threads = one float4 per thread over 1792 features
__global__ void k_prop(const float4* __restrict__ z, float4* __restrict__ out,
                       const float4* __restrict__ x0, int mode)
{
    int n = blockIdx.x;
    int tid = threadIdx.x;
    int e0 = g_rowstart[n], e1 = g_rowstart[n + 1];
    float4 acc = make_float4(0.f, 0.f, 0.f, 0.f);
    for (int e = e0; e < e1; e++) {
        int   c  = g_ccol[e];
        float nm = g_cnorm[e];
        float4 v = z[(long)c * F14 + tid];
        acc.x += nm * v.x; acc.y += nm * v.y;
        acc.z += nm * v.z; acc.w += nm * v.w;
    }
    if (mode) {  // Tx2 = 2*prop(Tx1) - Tx0
        float4 v0 = x0[(long)n * F14 + tid];
        acc.x = 2.f * acc.x - v0.x; acc.y = 2.f * acc.y - v0.y;
        acc.z = 2.f * acc.z - v0.z; acc.w = 2.f * acc.w - v0.w;
    }
    out[(long)n * F14 + tid] = acc;
}

// ---------------- fused Cheb GEMM: relu(Tx0 W0 + Tx1 W1 + Tx2 W2 + b) --------
__global__ void __launch_bounds__(512) k_cheb(const float* __restrict__ W,
                                              const float* __restrict__ bias)
{
    extern __shared__ float sm[];
    float* sW = sm;            // 3*64*64
    float* sb = sm + 3*64*64;  // 64
    for (int i = threadIdx.x; i < 3 * 64 * 64; i += 512) sW[i] = W[i];
    if (threadIdx.x < 64) sb[threadIdx.x] = bias[threadIdx.x];
    __syncthreads();

    int co = threadIdx.x & 63;
    int g  = threadIdx.x >> 6;
    int nb = blockIdx.x * 8 + g;

    const float4* x0 = (const float4*)(g_t1  + (long)nb * T1 * 64);
    const float4* x1 = (const float4*)(g_tx1 + (long)nb * T1 * 64);
    const float4* x2 = (const float4*)(g_tx2 + (long)nb * T1 * 64);

    float acc[T1];
#pragma unroll
    for (int t = 0; t < T1; t++) acc[t] = 0.f;

#pragma unroll
    for (int c4 = 0; c4 < 16; c4++) {
        float w0[4], w1[4], w2[4];
#pragma unroll
        for (int u = 0; u < 4; u++) {
            int c = c4 * 4 + u;
            w0[u] = sW[(0 * 64 + c) * 64 + co];
            w1[u] = sW[(1 * 64 + c) * 64 + co];
            w2[u] = sW[(2 * 64 + c) * 64 + co];
        }
#pragma unroll
        for (int t = 0; t < T1; t++) {
            float4 v0 = x0[t * 16 + c4];
            float4 v1 = x1[t * 16 + c4];
            float4 v2 = x2[t * 16 + c4];
            float a = acc[t];
            a += v0.x * w0[0] + v0.y * w0[1] + v0.z * w0[2] + v0.w * w0[3];
            a += v1.x * w1[0] + v1.y * w1[1] + v1.z * w1[2] + v1.w * w1[3];
            a += v2.x * w2[0] + v2.y * w2[1] + v2.z * w2[2] + v2.w * w2[3];
            acc[t] = a;
        }
    }

    float bv = sb[co];
    float* ob = g_t2 + (long)nb * T1 * 64 + co;
#pragma unroll
    for (int t = 0; t < T1; t++) {
        float v = acc[t] + bv;
        ob[t * 64] = (v > 0.f) ? v : 0.f;
    }
}

// ---------------- BN (channel axis = node) + final transpose -----------------
__global__ void k_bn(const float* __restrict__ gamma, const float* __restrict__ beta,
                     float* __restrict__ out)
{
    int n = blockIdx.x;
    const float* tp = g_t3 + (long)n * (BB * T2 * 64);  // 1536 elems
    float s = 0.f, s2 = 0.f;
    for (int i = threadIdx.x; i < BB * T2 * 64; i += 256) {
        float v = tp[i]; s += v; s2 += v * v;
    }
    __shared__ float rs[8], rs2[8];
    for (int o = 16; o; o >>= 1) {
        s  += __shfl_down_sync(0xffffffff, s,  o);
        s2 += __shfl_down_sync(0xffffffff, s2, o);
    }
    int lane = threadIdx.x & 31, wid = threadIdx.x >> 5;
    if (lane == 0) { rs[wid] = s; rs2[wid] = s2; }
    __syncthreads();
    __shared__ float smu, srstd;
    if (wid == 0) {
        float a  = (lane < 8) ? rs[lane]  : 0.f;
        float a2 = (lane < 8) ? rs2[lane] : 0.f;
        for (int o = 4; o; o >>= 1) {
            a  += __shfl_down_sync(0xffffffff, a,  o);
            a2 += __shfl_down_sync(0xffffffff, a2, o);
        }
        if (lane == 0) {
            float mu  = a / 1536.f;
            float var = a2 / 1536.f - mu * mu;
            smu = mu; srstd = rsqrtf(var + 1e-5f);
        }
    }
    __syncthreads();
    float mu = smu, rstd = srstd;
    float ga = gamma[n], be = beta[n];
    for (int i = threadIdx.x; i < BB * T2 * 64; i += 256) {
        float v = (tp[i] - mu) * rstd * ga + be;
        int c = i & 63;
        int t = (i >> 6) % T2;
        int b = i / (T2 * 64);
        out[(((long)b * T2 + t) * NN + n) * 64 + c] = v;
    }
}

// ---------------- launch -----------------------------------------------------
extern "C" void kernel_launch(void* const* d_in, const int* in_sizes, int n_in,
                              void* d_out, int out_size)
{
    const float* X    = (const float*)d_in[0];
    const int*   ei   = (const int*)  d_in[1];
    const float* ew   = (const float*)d_in[2];
    const float* t1w1 = (const float*)d_in[3];
    const float* t1b1 = (const float*)d_in[4];
    const float* t1w2 = (const float*)d_in[5];
    const float* t1b2 = (const float*)d_in[6];
    const float* t1w3 = (const float*)d_in[7];
    const float* t1b3 = (const float*)d_in[8];
    const float* chw  = (const float*)d_in[9];
    const float* chb  = (const float*)d_in[10];
    const float* t2w1 = (const float*)d_in[11];
    const float* t2b1 = (const float*)d_in[12];
    const float* t2w2 = (const float*)d_in[13];
    const float* t2b2 = (const float*)d_in[14];
    const float* t2w3 = (const float*)d_in[15];
    const float* t2b3 = (const float*)d_in[16];
    const float* gam  = (const float*)d_in[17];
    const float* bet  = (const float*)d_in[18];
    float* out = (float*)d_out;

    void *p_t1, *p_t2, *p_t3, *p_tx1, *p_tx2;
    cudaGetSymbolAddress(&p_t1,  g_t1);
    cudaGetSymbolAddress(&p_t2,  g_t2);
    cudaGetSymbolAddress(&p_t3,  g_t3);
    cudaGetSymbolAddress(&p_tx1, g_tx1);
    cudaGetSymbolAddress(&p_tx2, g_tx2);

    const int smem1 = 3 * CI1 * 3 * 64 * 4;   // 73728
    const int smem2 = 3 * CHH * 3 * 64 * 4;   // 147456
    const int smemC = (3 * 64 * 64 + 64) * 4; // 49408
    cudaFuncSetAttribute(k_tconv<CI1, TT>, cudaFuncAttributeMaxDynamicSharedMemorySize, smem1);
    cudaFuncSetAttribute(k_tconv<CHH, T1>, cudaFuncAttributeMaxDynamicSharedMemorySize, smem2);
    cudaFuncSetAttribute(k_cheb,           cudaFuncAttributeMaxDynamicSharedMemorySize, smemC);

    // graph preprocessing: degree -> norm -> CSR
    k_zero   <<<(NN + 255) / 256, 256>>>();
    k_deg    <<<EE / 256, 256>>>(ei, ew);
    k_dis    <<<(NN + 255) / 256, 256>>>();
    k_scan   <<<1, 1024>>>();
    k_scatter<<<EE / 256, 256>>>(ei, ew);

    // tconv1: X (b,t,n,ci) -> g_t1 node-major
    k_tconv<CI1, TT><<<NN * BB / 8, 512, smem1>>>(
        X, (long)TT * NN * CI1, (long)NN * CI1, (long)CI1,
        t1w1, t1b1, t1w2, t1b2, t1w3, t1b3, (float*)p_t1);

    // Cheb propagation
    k_prop<<<NN, F14>>>((const float4*)p_t1,  (float4*)p_tx1, (const float4*)p_t1, 0);
    k_prop<<<NN, F14>>>((const float4*)p_tx1, (float4*)p_tx2, (const float4*)p_t1, 1);

    // fused Cheb GEMM + bias + relu -> g_t2
    k_cheb<<<NN * BB / 8, 512, smemC>>>(chw, chb);

    // tconv2: g_t2 node-major -> g_t3 node-major
    k_tconv<CHH, T1><<<NN * BB / 8, 512, smem2>>>(
        (const float*)p_t2, (long)T1 * CHH, (long)CHH, (long)BB * T1 * CHH,
        t2w1, t2b1, t2w2, t2b2, t2w3, t2b3, (float*)p_t3);

    // BN per node + transpose to (B, T2, N, CO)
    k_bn<<<NN, 256>>>(gam, bet, out);
}

// round 2
// speedup vs baseline: 1.4842x; 1.4842x over previous
#include <cuda_runtime.h>
#include <math.h>

#define BB   2
#define TT   16
#define NN   2048
#define CI1  32
#define CHH  64
#define CO   64
#define KS   3
#define EE   32768
#define T1   14
#define T2   12
#define F1   (BB*T1*CHH)   /* 1792 floats per node for propagation */
#define F14  (F1/4)        /* 448 float4 */

#define GROUPS   14
#define THREADS  (GROUPS*32)
#define NB_TOTAL (NN*BB)
#define GRID     ((NB_TOTAL + GROUPS - 1) / GROUPS)

typedef unsigned long long u64;

__device__ __forceinline__ u64 pk2(float lo, float hi) {
    u64 r; asm("mov.b64 %0, {%1, %2};" : "=l"(r) : "f"(lo), "f"(hi)); return r;
}
__device__ __forceinline__ u64 fma2(u64 a, u64 b, u64 c) {
    u64 r; asm("fma.rn.f32x2 %0, %1, %2, %3;" : "=l"(r) : "l"(a), "l"(b), "l"(c)); return r;
}
__device__ __forceinline__ float2 upk2(u64 a) {
    float2 f; asm("mov.b64 {%0, %1}, %2;" : "=f"(f.x), "=f"(f.y) : "l"(a)); return f;
}

// ---------------- scratch (device globals; no allocations allowed) ----------
__device__ __align__(16) float g_t1 [NN*BB*T1*CHH];
__device__ __align__(16) float g_tx1[NN*BB*T1*CHH];
__device__ __align__(16) float g_tx2[NN*BB*T1*CHH];
__device__ __align__(16) float g_t2 [NN*BB*T1*CHH];
__device__ __align__(16) float g_t3 [NN*BB*T2*CO];
__device__ float g_deg[NN];
__device__ float g_dis[NN];
__device__ int   g_rowcount[NN];
__device__ int   g_rowstart[NN+1];
__device__ int   g_cursor[NN];
__device__ int   g_ccol[EE];
__device__ float g_cnorm[EE];

// ---------------- graph preprocessing ---------------------------------------
__global__ void k_zero() {
    int i = blockIdx.x * blockDim.x + threadIdx.x;
    if (i < NN) { g_deg[i] = 0.f; g_rowcount[i] = 0; g_cursor[i] = 0; }
}

__global__ void k_deg(const int* __restrict__ ei, const float* __restrict__ ew) {
    int e = blockIdx.x * blockDim.x + threadIdx.x;
    if (e < EE) {
        int r = ei[e], c = ei[EE + e];
        float w = (r == c) ? 0.f : ew[e];
        atomicAdd(&g_deg[r], w);
        atomicAdd(&g_rowcount[r], 1);
    }
}

__global__ void k_dis() {
    int i = blockIdx.x * blockDim.x + threadIdx.x;
    if (i < NN) {
        float d = g_deg[i];
        g_dis[i] = (d > 0.f) ? rsqrtf(d) : 0.f;
    }
}

// warp-shuffle scan: 1024 threads, 2 counts each
__global__ void k_scan() {
    int tid = threadIdx.x;
    int v0 = g_rowcount[2 * tid], v1 = g_rowcount[2 * tid + 1];
    int s  = v0 + v1;
    int lane = tid & 31, wid = tid >> 5;
    int sc = s;
#pragma unroll
    for (int o = 1; o < 32; o <<= 1) {
        int t = __shfl_up_sync(0xffffffffu, sc, o);
        if (lane >= o) sc += t;
    }
    __shared__ int ws[32];
    if (lane == 31) ws[wid] = sc;
    __syncthreads();
    if (wid == 0) {
        int w = ws[lane];
#pragma unroll
        for (int o = 1; o < 32; o <<= 1) {
            int t = __shfl_up_sync(0xffffffffu, w, o);
            if (lane >= o) w += t;
        }
        ws[lane] = w;
    }
    __syncthreads();
    int base = ((wid > 0) ? ws[wid - 1] : 0) + sc - s;  // exclusive prefix of pair
    g_rowstart[2 * tid + 1] = base + v0;
    g_rowstart[2 * tid + 2] = base + v0 + v1;
    if (tid == 0) g_rowstart[0] = 0;
}

__global__ void k_scatter(const int* __restrict__ ei, const float* __restrict__ ew) {
    int e = blockIdx.x * blockDim.x + threadIdx.x;
    if (e < EE) {
        int r = ei[e], c = ei[EE + e];
        float w = (r == c) ? 0.f : ew[e];
        int pos = g_rowstart[r] + atomicAdd(&g_cursor[r], 1);
        g_ccol[pos]  = c;
        g_cnorm[pos] = -g_dis[r] * w * g_dis[c];
    }
}

// ---------------- gated temporal conv, f32x2-packed over channel pairs -------
// 448 threads = 14 (n,b) groups x 32 pair-lanes. Lane p handles channels 2p,2p+1.
template<int CI, int TIN>
__global__ void __launch_bounds__(THREADS) k_tconv(
    const float* __restrict__ x, long sb, long st, long sn,
    const float* __restrict__ w1, const float* __restrict__ bb1,
    const float* __restrict__ w2, const float* __restrict__ bb2,
    const float* __restrict__ w3, const float* __restrict__ bb3,
    float* __restrict__ out)
{
    constexpr int TOUT = TIN - 2;
    extern __shared__ char smraw[];
    u64* sw = (u64*)smraw;  // [3][CI][3][32] packed channel pairs
    for (int idx = threadIdx.x; idx < 3 * CI * 3 * 32; idx += THREADS) {
        int p = idx & 31;
        int rest = idx >> 5;
        int k = rest % 3; rest /= 3;
        int ci = rest % CI;
        int j  = rest / CI;
        const float* wj = (j == 0) ? w1 : ((j == 1) ? w2 : w3);
        float lo = wj[((2 * p)     * CI + ci) * KS + k];
        float hi = wj[((2 * p + 1) * CI + ci) * KS + k];
        sw[idx] = pk2(lo, hi);
    }
    __syncthreads();

    int p  = threadIdx.x & 31;
    int g  = threadIdx.x >> 5;
    int nb = blockIdx.x * GROUPS + g;
    if (nb >= NB_TOTAL) return;
    int n  = nb >> 1, b = nb & 1;

    u64 acc[3][TOUT];
#pragma unroll
    for (int j = 0; j < 3; j++)
#pragma unroll
        for (int t = 0; t < TOUT; t++) acc[j][t] = 0ull;

    const float* xb = x + (long)b * sb + (long)n * sn;

    for (int ci = 0; ci < CI; ci++) {
        u64 w[3][3];
#pragma unroll
        for (int j = 0; j < 3; j++)
#pragma unroll
            for (int k = 0; k < 3; k++)
                w[j][k] = sw[((j * CI + ci) * 3 + k) * 32 + p];
#pragma unroll
        for (int ti = 0; ti < TIN; ti++) {
            float xv = __ldg(xb + (long)ti * st + ci);
            u64 xx = pk2(xv, xv);
#pragma unroll
            for (int k = 0; k < 3; k++) {
                int to = ti - k;
                if (to >= 0 && to < TOUT) {
                    acc[0][to] = fma2(xx, w[0][k], acc[0][to]);
                    acc[1][to] = fma2(xx, w[1][k], acc[1][to]);
                    acc[2][to] = fma2(xx, w[2][k], acc[2][to]);
                }
            }
        }
    }

    float2 bv1 = __ldg((const float2*)bb1 + p);
    float2 bv2 = __ldg((const float2*)bb2 + p);
    float2 bv3 = __ldg((const float2*)bb3 + p);
    float* ob = out + ((long)nb * TOUT) * 64 + 2 * p;
#pragma unroll
    for (int t = 0; t < TOUT; t++) {
        float2 a1 = upk2(acc[0][t]);
        float2 a2 = upk2(acc[1][t]);
        float2 a3 = upk2(acc[2][t]);
        float zx = a2.x + bv2.x, zy = a2.y + bv2.y;
        float sx = __fdividef(1.f, 1.f + __expf(-zx));
        float sy = __fdividef(1.f, 1.f + __expf(-zy));
        float vx = a1.x + bv1.x + sx + a3.x + bv3.x;
        float vy = a1.y + bv1.y + sy + a3.y + bv3.y;
        vx = (vx > 0.f) ? vx : 0.f;
        vy = (vy > 0.f) ? vy : 0.f;
        *(float2*)(ob + t * 64) = make_float2(vx, vy);
    }
}

// ---------------- ChebConv propagation (CSR gather) --------------------------
__global__ void k_prop(const float4* __restrict__ z, float4* __restrict__ out,
                       const float4* __restrict__ x0, int mode)
{
    int n = blockIdx.x;
    int tid = threadIdx.x;
    int e0 = g_rowstart[n], e1 = g_rowstart[n + 1];
    float4 acc = make_float4(0.f, 0.f, 0.f, 0.f);
    for (int e = e0; e < e1; e++) {
        int   c  = __ldg(&g_ccol[e]);
        float nm = __ldg(&g_cnorm[e]);
        float4 v = __ldg(&z[(long)c * F14 + tid]);
        acc.x += nm * v.x; acc.y += nm * v.y;
        acc.z += nm * v.z; acc.w += nm * v.w;
    }
    if (mode) {  // Tx2 = 2*prop(Tx1) - Tx0
        float4 v0 = __ldg(&x0[(long)n * F14 + tid]);
        acc.x = 2.f * acc.x - v0.x; acc.y = 2.f * acc.y - v0.y;
        acc.z = 2.f * acc.z - v0.z; acc.w = 2.f * acc.w - v0.w;
    }
    out[(long)n * F14 + tid] = acc;
}

// ---------------- fused Cheb GEMM: relu(Tx0 W0 + Tx1 W1 + Tx2 W2 + b) --------
// 448 threads = 14 groups x 32 pair-lanes over output channels
__global__ void __launch_bounds__(THREADS) k_cheb(const float* __restrict__ W,
                                                  const float* __restrict__ bias)
{
    extern __shared__ char smraw[];
    u64* sW = (u64*)smraw;  // [3][64][32] packed co pairs
    for (int idx = threadIdx.x; idx < 3 * 64 * 32; idx += THREADS) {
        int p = idx & 31;
        int jc = idx >> 5;      // j*64 + c
        float lo = W[jc * 64 + 2 * p];
        float hi = W[jc * 64 + 2 * p + 1];
        sW[idx] = pk2(lo, hi);
    }
    __syncthreads();

    int p  = threadIdx.x & 31;
    int g  = threadIdx.x >> 5;
    int nb = blockIdx.x * GROUPS + g;
    if (nb >= NB_TOTAL) return;

    const float4* x0 = (const float4*)(g_t1  + (long)nb * T1 * 64);
    const float4* x1 = (const float4*)(g_tx1 + (long)nb * T1 * 64);
    const float4* x2 = (const float4*)(g_tx2 + (long)nb * T1 * 64);

    u64 acc[T1];
#pragma unroll
    for (int t = 0; t < T1; t++) acc[t] = 0ull;

#pragma unroll
    for (int c4 = 0; c4 < 16; c4++) {
        u64 w0[4], w1[4], w2[4];
#pragma unroll
        for (int u = 0; u < 4; u++) {
            int c = c4 * 4 + u;
            w0[u] = sW[(0 * 64 + c) * 32 + p];
            w1[u] = sW[(1 * 64 + c) * 32 + p];
            w2[u] = sW[(2 * 64 + c) * 32 + p];
        }
#pragma unroll
        for (int t = 0; t < T1; t++) {
            float4 v0 = __ldg(&x0[t * 16 + c4]);
            float4 v1 = __ldg(&x1[t * 16 + c4]);
            float4 v2 = __ldg(&x2[t * 16 + c4]);
            u64 a = acc[t];
            a = fma2(pk2(v0.x, v0.x), w0[0], a);
            a = fma2(pk2(v0.y, v0.y), w0[1], a);
            a = fma2(pk2(v0.z, v0.z), w0[2], a);
            a = fma2(pk2(v0.w, v0.w), w0[3], a);
            a = fma2(pk2(v1.x, v1.x), w1[0], a);
            a = fma2(pk2(v1.y, v1.y), w1[1], a);
            a = fma2(pk2(v1.z, v1.z), w1[2], a);
            a = fma2(pk2(v1.w, v1.w), w1[3], a);
            a = fma2(pk2(v2.x, v2.x), w2[0], a);
            a = fma2(pk2(v2.y, v2.y), w2[1], a);
            a = fma2(pk2(v2.z, v2.z), w2[2], a);
            a = fma2(pk2(v2.w, v2.w), w2[3], a);
            acc[t] = a;
        }
    }

    float2 bv = __ldg((const float2*)bias + p);
    float* ob = g_t2 + (long)nb * T1 * 64 + 2 * p;
#pragma unroll
    for (int t = 0; t < T1; t++) {
        float2 a = upk2(acc[t]);
        float vx = a.x + bv.x, vy = a.y + bv.y;
        vx = (vx > 0.f) ? vx : 0.f;
        vy = (vy > 0.f) ? vy : 0.f;
        *(float2*)(ob + t * 64) = make_float2(vx, vy);
    }
}

// ---------------- BN (channel axis = node) + final transpose -----------------
__global__ void k_bn(const float* __restrict__ gamma, const float* __restrict__ beta,
                     float* __restrict__ out)
{
    int n = blockIdx.x;
    const float* tp = g_t3 + (long)n * (BB * T2 * 64);  // 1536 elems
    float s = 0.f, s2 = 0.f;
    for (int i = threadIdx.x; i < BB * T2 * 64; i += 256) {
        float v = tp[i]; s += v; s2 += v * v;
    }
    __shared__ float rs[8], rs2[8];
    for (int o = 16; o; o >>= 1) {
        s  += __shfl_down_sync(0xffffffff, s,  o);
        s2 += __shfl_down_sync(0xffffffff, s2, o);
    }
    int lane = threadIdx.x & 31, wid = threadIdx.x >> 5;
    if (lane == 0) { rs[wid] = s; rs2[wid] = s2; }
    __syncthreads();
    __shared__ float smu, srstd;
    if (wid == 0) {
        float a  = (lane < 8) ? rs[lane]  : 0.f;
        float a2 = (lane < 8) ? rs2[lane] : 0.f;
        for (int o = 4; o; o >>= 1) {
            a  += __shfl_down_sync(0xffffffff, a,  o);
            a2 += __shfl_down_sync(0xffffffff, a2, o);
        }
        if (lane == 0) {
            float mu  = a / 1536.f;
            float var = a2 / 1536.f - mu * mu;
            smu = mu; srstd = rsqrtf(var + 1e-5f);
        }
    }
    __syncthreads();
    float mu = smu, rstd = srstd;
    float ga = gamma[n], be = beta[n];
    for (int i = threadIdx.x; i < BB * T2 * 64; i += 256) {
        float v = (tp[i] - mu) * rstd * ga + be;
        int c = i & 63;
        int t = (i >> 6) % T2;
        int b = i / (T2 * 64);
        out[(((long)b * T2 + t) * NN + n) * 64 + c] = v;
    }
}

// ---------------- launch -----------------------------------------------------
extern "C" void kernel_launch(void* const* d_in, const int* in_sizes, int n_in,
                              void* d_out, int out_size)
{
    const float* X    = (const float*)d_in[0];
    const int*   ei   = (const int*)  d_in[1];
    const float* ew   = (const float*)d_in[2];
    const float* t1w1 = (const float*)d_in[3];
    const float* t1b1 = (const float*)d_in[4];
    const float* t1w2 = (const float*)d_in[5];
    const float* t1b2 = (const float*)d_in[6];
    const float* t1w3 = (const float*)d_in[7];
    const float* t1b3 = (const float*)d_in[8];
    const float* chw  = (const float*)d_in[9];
    const float* chb  = (const float*)d_in[10];
    const float* t2w1 = (const float*)d_in[11];
    const float* t2b1 = (const float*)d_in[12];
    const float* t2w2 = (const float*)d_in[13];
    const float* t2b2 = (const float*)d_in[14];
    const float* t2w3 = (const float*)d_in[15];
    const float* t2b3 = (const float*)d_in[16];
    const float* gam  = (const float*)d_in[17];
    const float* bet  = (const float*)d_in[18];
    float* out = (float*)d_out;

    void *p_t1, *p_t2, *p_t3, *p_tx1, *p_tx2;
    cudaGetSymbolAddress(&p_t1,  g_t1);
    cudaGetSymbolAddress(&p_t2,  g_t2);
    cudaGetSymbolAddress(&p_t3,  g_t3);
    cudaGetSymbolAddress(&p_tx1, g_tx1);
    cudaGetSymbolAddress(&p_tx2, g_tx2);

    const int smem1 = 3 * CI1 * 3 * 32 * 8;   // 73728
    const int smem2 = 3 * CHH * 3 * 32 * 8;   // 147456
    const int smemC = 3 * 64 * 32 * 8;        // 49152
    cudaFuncSetAttribute(k_tconv<CI1, TT>, cudaFuncAttributeMaxDynamicSharedMemorySize, smem1);
    cudaFuncSetAttribute(k_tconv<CHH, T1>, cudaFuncAttributeMaxDynamicSharedMemorySize, smem2);
    cudaFuncSetAttribute(k_cheb,           cudaFuncAttributeMaxDynamicSharedMemorySize, smemC);

    // graph preprocessing: degree -> norm -> CSR
    k_zero   <<<(NN + 255) / 256, 256>>>();
    k_deg    <<<EE / 256, 256>>>(ei, ew);
    k_dis    <<<(NN + 255) / 256, 256>>>();
    k_scan   <<<1, 1024>>>();
    k_scatter<<<EE / 256, 256>>>(ei, ew);

    // tconv1: X (b,t,n,ci) -> g_t1 node-major
    k_tconv<CI1, TT><<<GRID, THREADS, smem1>>>(
        X, (long)TT * NN * CI1, (long)NN * CI1, (long)CI1,
        t1w1, t1b1, t1w2, t1b2, t1w3, t1b3, (float*)p_t1);

    // Cheb propagation
    k_prop<<<NN, F14>>>((const float4*)p_t1,  (float4*)p_tx1, (const float4*)p_t1, 0);
    k_prop<<<NN, F14>>>((const float4*)p_tx1, (float4*)p_tx2, (const float4*)p_t1, 1);

    // fused Cheb GEMM + bias + relu -> g_t2
    k_cheb<<<GRID, THREADS, smemC>>>(chw, chb);

    // tconv2: g_t2 node-major -> g_t3 node-major
    k_tconv<CHH, T1><<<GRID, THREADS, smem2>>>(
        (const float*)p_t2, (long)T1 * CHH, (long)CHH, (long)BB * T1 * CHH,
        t2w1, t2b1, t2w2, t2b2, t2w3, t2b3, (float*)p_t3);

    // BN per node + transpose to (B, T2, N, CO)
    k_bn<<<NN, 256>>>(gam, bet, out);
}